// round 1
// baseline (speedup 1.0000x reference)
#include <cuda_runtime.h>
#include <cuda_bf16.h>
#include <math.h>

// ---------------- problem sizes ----------------
#define NMS_N   256
#define HW      16384          // 128*128
#define WORDS   512            // 16384/32
#define NB      64             // batch for CRF
#define NPIX    (NB*HW)        // 1,048,576

// ---------------- device scratch (static, no allocation) ----------------
__device__ unsigned int g_packedT[WORDS * NMS_N];      // [word][mask]
__device__ float        g_sums[NMS_N];
__device__ float        g_dmat[NMS_N * NMS_N];         // [j][i]
__device__ float        g_comp[NMS_N];
__device__ float        g_kernelw[(size_t)NB * 9 * HW];// [b][k][pix]
__device__ unsigned char g_state[2][NPIX];

// ================= NMS =================

__global__ void pack_kernel(const float* __restrict__ seg) {
    int m   = blockIdx.x;          // mask index
    int tid = threadIdx.x;         // 512 threads
    int warp = tid >> 5, lane = tid & 31;
    int cnt = 0;
    for (int w = warp; w < WORDS; w += 16) {
        float v = seg[(size_t)m * HW + w * 32 + lane];
        unsigned bal = __ballot_sync(0xffffffffu, v != 0.0f);
        if (lane == 0) {
            g_packedT[w * NMS_N + m] = bal;
            cnt += __popc(bal);
        }
    }
    __shared__ int scnt[16];
    if (lane == 0) scnt[warp] = cnt;
    __syncthreads();
    if (tid == 0) {
        int t = 0;
        for (int i = 0; i < 16; ++i) t += scnt[i];
        g_sums[m] = (float)t;
    }
}

__global__ void nms_iou_kernel(const int* __restrict__ labels) {
    int j = blockIdx.x;            // column
    int i = threadIdx.x;           // row (256 threads)
    __shared__ unsigned int smj[WORDS];
    for (int w = i; w < WORDS; w += NMS_N) smj[w] = g_packedT[w * NMS_N + j];
    __syncthreads();

    float d = 0.0f;
    if (i < j && labels[i] == labels[j]) {
        int inter = 0;
        #pragma unroll 4
        for (int w = 0; w < WORDS; ++w)
            inter += __popc(g_packedT[w * NMS_N + i] & smj[w]);
        float fi  = (float)inter;
        float uni = g_sums[j] + g_sums[i] - fi;
        d = fi / uni;
    }
    g_dmat[j * NMS_N + i] = d;

    __shared__ float red[NMS_N];
    red[i] = d;
    __syncthreads();
    for (int s = NMS_N / 2; s > 0; s >>= 1) {
        if (i < s) red[i] = fmaxf(red[i], red[i + s]);
        __syncthreads();
    }
    if (i == 0) g_comp[j] = red[0];
}

__global__ void nms_coef_kernel(const float* __restrict__ cate_scores,
                                float* __restrict__ out_scores) {
    int j = blockIdx.x;
    int i = threadIdx.x;
    float d  = g_dmat[j * NMS_N + i];
    float ci = g_comp[i];
    float v  = expf(-2.0f * d * d) / expf(-2.0f * ci * ci);
    __shared__ float red[NMS_N];
    red[i] = v;
    __syncthreads();
    for (int s = NMS_N / 2; s > 0; s >>= 1) {
        if (i < s) red[i] = fminf(red[i], red[i + s]);
        __syncthreads();
    }
    if (i == 0) out_scores[j] = cate_scores[j] * red[0];
}

// ================= CRF =================

// weights + initial state
__global__ void crf_weights_kernel(const float* __restrict__ fm,
                                   const float* __restrict__ x,
                                   const float* __restrict__ tg) {
    int idx = blockIdx.x * blockDim.x + threadIdx.x;
    if (idx >= NPIX) return;
    int b   = idx >> 14;
    int pix = idx & (HW - 1);
    int h   = pix >> 7, w = pix & 127;

    const float* fb = fm + (size_t)b * 3 * HW;
    float c0 = fb[pix] + 10.0f;
    float c1 = fb[HW + pix] + 10.0f;
    float c2 = fb[2 * HW + pix] + 10.0f;

    float* kwb = g_kernelw + (size_t)b * 9 * HW;
    #pragma unroll
    for (int k = 0; k < 9; ++k) {
        int di = k / 3 - 1, dj = k % 3 - 1;
        int hh = h + di, ww = w + dj;
        float n0 = 0.0f, n1 = 0.0f, n2 = 0.0f;
        if (hh >= 0 && hh < 128 && ww >= 0 && ww < 128) {
            int np = hh * 128 + ww;
            n0 = fb[np] + 10.0f;
            n1 = fb[HW + np] + 10.0f;
            n2 = fb[2 * HW + np] + 10.0f;
        }
        float d0 = n0 - c0, d1 = n1 - c1, d2 = n2 - c2;
        float ss = d0 * d0 + d1 * d1 + d2 * d2;
        float color = -(ss) * 2.0f;                 // / (2*0.5^2)
        float spat  = (float)(di * di + dj * dj) / 1800.0f;  // const-folded
        kwb[k * HW + pix] = 3.0f * expf(color - spat);
    }

    float xv = x[idx], tv = tg[idx];
    g_state[0][idx] = (xv * tv > 0.5f) ? 0 : 1;
}

// state: 0 = (ret0=lo-ish, ret1=hi-ish)  "mask on"
//        1 = (ret0=hi-ish, ret1=lo-ish)  "mask off"
//        2 = both low, 3 = both high
struct LTab { float L0[4]; float L1[4]; };

__global__ void crf_iter_kernel(int cur, LTab lt,
                                const float* __restrict__ tg,
                                float* __restrict__ out_masks) {
    int idx = blockIdx.x * blockDim.x + threadIdx.x;
    if (idx >= NPIX) return;
    int b   = idx >> 14;
    int pix = idx & (HW - 1);
    int h   = pix >> 7, w = pix & 127;

    const unsigned char* sb = g_state[cur] + (size_t)b * HW;
    const float* kwb = g_kernelw + (size_t)b * 9 * HW;

    float a0 = 0.0f, a1 = 0.0f;
    #pragma unroll
    for (int k = 0; k < 9; ++k) {
        int di = k / 3 - 1, dj = k % 3 - 1;
        int hh = h + di, ww = w + dj;
        if (hh >= 0 && hh < 128 && ww >= 0 && ww < 128) {
            int st = sb[hh * 128 + ww];
            float wv = kwb[k * HW + pix];
            a0 += wv * lt.L0[st];
            a1 += wv * lt.L1[st];
        }
    }
    float t  = tg[idx];
    float f0 = expf(-a0) + 1e-6f;
    float f1 = expf(-a1) * t + 1e-6f;
    float s  = f0 + f1;
    float fn0 = f0 / s;
    float fn1 = f1 / s;
    int ns = (fn1 > 0.5f) ? ((fn0 > 0.5f) ? 3 : 0)
                          : ((fn0 > 0.5f) ? 1 : 2);
    g_state[cur ^ 1][idx] = (unsigned char)ns;
    if (out_masks)
        out_masks[idx] = (ns == 0 || ns == 3) ? 1.0f : 0.0f;
}

__global__ void valid_kernel(int finalBuf, float* __restrict__ out_valid) {
    int b = blockIdx.x;
    int tid = threadIdx.x;     // 256
    const unsigned char* sb = g_state[finalBuf] + (size_t)b * HW;
    int cnt = 0;
    for (int p = tid; p < HW; p += 256) {
        int s = sb[p];
        cnt += (s == 0 || s == 3) ? 1 : 0;
    }
    __shared__ int red[256];
    red[tid] = cnt;
    __syncthreads();
    for (int s = 128; s > 0; s >>= 1) {
        if (tid < s) red[tid] += red[tid + s];
        __syncthreads();
    }
    if (tid == 0) {
        float c = (float)red[0];
        out_valid[b] = (c >= 16384.0f * 0.05f && c <= 16384.0f * 0.95f) ? 1.0f : 0.0f;
    }
}

// ================= launch =================

extern "C" void kernel_launch(void* const* d_in, const int* in_sizes, int n_in,
                              void* d_out, int out_size) {
    const float* seg_masks   = (const float*)d_in[0];   // 256*128*128
    const float* cate_scores = (const float*)d_in[1];   // 256
    const float* feature_map = (const float*)d_in[2];   // 64*3*128*128
    const float* x           = (const float*)d_in[3];   // 64*1*128*128
    const float* targets     = (const float*)d_in[4];   // 64*1*128*128
    const int*   cate_labels = (const int*)d_in[5];     // 256 (int32 canonicalized)

    float* out_scores = (float*)d_out;                       // [256]
    float* out_masks  = out_scores + NMS_N;                  // [64*128*128]
    float* out_valid  = out_masks + NPIX;                    // [64]

    // ---- NMS ----
    pack_kernel<<<NMS_N, 512>>>(seg_masks);
    nms_iou_kernel<<<NMS_N, NMS_N>>>(cate_labels);
    nms_coef_kernel<<<NMS_N, NMS_N>>>(cate_scores, out_scores);

    // ---- CRF ----
    int threads = 256;
    int blocks  = (NPIX + threads - 1) / threads;
    crf_weights_kernel<<<blocks, threads>>>(feature_map, x, targets);

    // float constants matching reference arithmetic
    const float lo    = 0.45f;
    const float delta = (float)(1.0 - 2.0 * 0.45);  // 0.1f
    const float hi    = delta + lo;                 // xt "on" value
    const float Llo   = -logf(lo);
    const float Lhi   = -logf(hi);

    LTab init;  // iteration 1: ret0 = 1 - xt (slightly different constants)
    init.L0[0] = -logf(1.0f - hi); init.L1[0] = Lhi;
    init.L0[1] = -logf(1.0f - lo); init.L1[1] = Llo;
    init.L0[2] = Llo;              init.L1[2] = Llo;  // unused
    init.L0[3] = Lhi;              init.L1[3] = Lhi;  // unused

    LTab std;   // iterations 2..10: ret in {lo, hi} per channel
    std.L0[0] = Llo; std.L1[0] = Lhi;
    std.L0[1] = Lhi; std.L1[1] = Llo;
    std.L0[2] = Llo; std.L1[2] = Llo;
    std.L0[3] = Lhi; std.L1[3] = Lhi;

    int cur = 0;
    for (int it = 0; it < 10; ++it) {
        const LTab& lt = (it == 0) ? init : std;
        float* om = (it == 9) ? out_masks : nullptr;
        crf_iter_kernel<<<blocks, threads>>>(cur, lt, targets, om);
        cur ^= 1;
    }

    valid_kernel<<<NB, 256>>>(cur, out_valid);
}

// round 2
// speedup vs baseline: 3.2917x; 3.2917x over previous
#include <cuda_runtime.h>
#include <cuda_bf16.h>
#include <math.h>

// ---------------- problem sizes ----------------
#define NMS_N   256
#define HW      16384          // 128*128
#define WORDS   512            // 16384/32
#define NB      64             // batch for CRF
#define NPIX    (NB*HW)        // 1,048,576

// ---------------- device scratch (static, no allocation) ----------------
__device__ unsigned int g_packedT[WORDS * NMS_N];      // [word][mask]
__device__ float        g_sums[NMS_N];
__device__ float        g_dmat[NMS_N * NMS_N];         // [j][i]
__device__ float        g_comp[NMS_N];
__device__ float        g_w[(size_t)NB * 8 * HW];      // [b][k(8)][pix], center excluded
__device__ float        g_thresh[NPIX];                // t ? S/2 : +INF
__device__ float        g_state[2][NPIX + 256];        // 128-float pad each side, zero-init

// ================= NMS =================

__global__ void pack_kernel(const float* __restrict__ seg) {
    int m   = blockIdx.x;
    int tid = threadIdx.x;         // 512 threads
    int warp = tid >> 5, lane = tid & 31;
    int cnt = 0;
    for (int w = warp; w < WORDS; w += 16) {
        float v = seg[(size_t)m * HW + w * 32 + lane];
        unsigned bal = __ballot_sync(0xffffffffu, v != 0.0f);
        if (lane == 0) {
            g_packedT[w * NMS_N + m] = bal;
            cnt += __popc(bal);
        }
    }
    __shared__ int scnt[16];
    if (lane == 0) scnt[warp] = cnt;
    __syncthreads();
    if (tid == 0) {
        int t = 0;
        for (int i = 0; i < 16; ++i) t += scnt[i];
        g_sums[m] = (float)t;
    }
}

__global__ void nms_iou_kernel(const int* __restrict__ labels) {
    int j = blockIdx.x;
    int i = threadIdx.x;
    __shared__ unsigned int smj[WORDS];
    for (int w = i; w < WORDS; w += NMS_N) smj[w] = g_packedT[w * NMS_N + j];
    __syncthreads();

    float d = 0.0f;
    if (i < j && labels[i] == labels[j]) {
        int inter = 0;
        #pragma unroll 4
        for (int w = 0; w < WORDS; ++w)
            inter += __popc(g_packedT[w * NMS_N + i] & smj[w]);
        float fi  = (float)inter;
        float uni = g_sums[j] + g_sums[i] - fi;
        d = fi / uni;
    }
    g_dmat[j * NMS_N + i] = d;

    __shared__ float red[NMS_N];
    red[i] = d;
    __syncthreads();
    for (int s = NMS_N / 2; s > 0; s >>= 1) {
        if (i < s) red[i] = fmaxf(red[i], red[i + s]);
        __syncthreads();
    }
    if (i == 0) g_comp[j] = red[0];
}

__global__ void nms_coef_kernel(const float* __restrict__ cate_scores,
                                float* __restrict__ out_scores) {
    int j = blockIdx.x;
    int i = threadIdx.x;
    float d  = g_dmat[j * NMS_N + i];
    float ci = g_comp[i];
    float v  = expf(-2.0f * d * d) / expf(-2.0f * ci * ci);
    __shared__ float red[NMS_N];
    red[i] = v;
    __syncthreads();
    for (int s = NMS_N / 2; s > 0; s >>= 1) {
        if (i < s) red[i] = fminf(red[i], red[i + s]);
        __syncthreads();
    }
    if (i == 0) out_scores[j] = cate_scores[j] * red[0];
}

// ================= CRF =================

// weights (8 dirs, center is constant 3.0), threshold, initial state
__global__ void crf_weights_kernel(const float* __restrict__ fm,
                                   const float* __restrict__ x,
                                   const float* __restrict__ tg) {
    int idx = blockIdx.x * blockDim.x + threadIdx.x;
    if (idx >= NPIX) return;
    int b   = idx >> 14;
    int pix = idx & (HW - 1);
    int h   = pix >> 7, w = pix & 127;

    const float* fb = fm + (size_t)b * 3 * HW;
    float c0 = fb[pix] + 10.0f;
    float c1 = fb[HW + pix] + 10.0f;
    float c2 = fb[2 * HW + pix] + 10.0f;

    float* wb = g_w + (size_t)b * 8 * HW;
    float S = 3.0f;  // center weight is exactly 3.0
    #pragma unroll
    for (int k = 0; k < 9; ++k) {
        if (k == 4) continue;
        int di = k / 3 - 1, dj = k % 3 - 1;
        int hh = h + di, ww = w + dj;
        float n0 = 0.0f, n1 = 0.0f, n2 = 0.0f;
        if (hh >= 0 && hh < 128 && ww >= 0 && ww < 128) {
            int np = hh * 128 + ww;
            n0 = fb[np] + 10.0f;
            n1 = fb[HW + np] + 10.0f;
            n2 = fb[2 * HW + np] + 10.0f;
        }
        float d0 = n0 - c0, d1 = n1 - c1, d2 = n2 - c2;
        float ss = d0 * d0 + d1 * d1 + d2 * d2;
        float color = -ss * 2.0f;                           // /(2*0.5^2)
        float spat  = (float)(di * di + dj * dj) / 1800.0f; // /(2*30^2)
        float wv = 3.0f * expf(color - spat);               // 0 for OOB (underflow)
        int kk = (k < 4) ? k : k - 1;
        wb[kk * HW + pix] = wv;
        S += wv;
    }

    float xv = x[idx], tv = tg[idx];
    g_thresh[idx] = (tv > 0.5f) ? (0.5f * S) : __int_as_float(0x7f800000);
    g_state[0][128 + idx] = (xv * tv > 0.5f) ? 1.0f : 0.0f;
}

// One CRF iteration: 4 pixels per thread, branch-free.
// new_state = (sum_{on neighbors} w) > thresh   (thresh = t? S/2 : INF)
__global__ void crf_iter_kernel(const float* __restrict__ sin,
                                float* __restrict__ sout,
                                float* __restrict__ out_masks) {
    int t4 = blockIdx.x * blockDim.x + threadIdx.x;
    if (t4 >= NPIX / 4) return;
    int idx = t4 << 2;                 // aligned group of 4 pixels
    int b   = idx >> 14;
    int pix = idx & (HW - 1);
    int h   = pix >> 7;

    // row indices (clamped; OOB direction weights are 0 so values don't matter)
    int up = (h > 0)   ? idx - 128 : idx;
    int dn = (h < 127) ? idx + 128 : idx;

    float4 cu = *(const float4*)(sin + up);
    float4 cm = *(const float4*)(sin + idx);
    float4 cd = *(const float4*)(sin + dn);
    float lu = sin[up - 1],  ru = sin[up + 4];
    float lm = sin[idx - 1], rm = sin[idx + 4];
    float ld = sin[dn - 1],  rd = sin[dn + 4];

    float tw[6] = {lu, cu.x, cu.y, cu.z, cu.w, ru};
    float mw[6] = {lm, cm.x, cm.y, cm.z, cm.w, rm};
    float bw[6] = {ld, cd.x, cd.y, cd.z, cd.w, rd};

    const float* wbase = g_w + (size_t)b * 8 * HW + pix;
    float4 w0 = *(const float4*)(wbase + 0 * HW);
    float4 w1 = *(const float4*)(wbase + 1 * HW);
    float4 w2 = *(const float4*)(wbase + 2 * HW);
    float4 w3 = *(const float4*)(wbase + 3 * HW);
    float4 w4 = *(const float4*)(wbase + 4 * HW);
    float4 w5 = *(const float4*)(wbase + 5 * HW);
    float4 w6 = *(const float4*)(wbase + 6 * HW);
    float4 w7 = *(const float4*)(wbase + 7 * HW);
    float wa[8][4] = {
        {w0.x, w0.y, w0.z, w0.w}, {w1.x, w1.y, w1.z, w1.w},
        {w2.x, w2.y, w2.z, w2.w}, {w3.x, w3.y, w3.z, w3.w},
        {w4.x, w4.y, w4.z, w4.w}, {w5.x, w5.y, w5.z, w5.w},
        {w6.x, w6.y, w6.z, w6.w}, {w7.x, w7.y, w7.z, w7.w}};

    float4 th = *(const float4*)(g_thresh + idx);
    float tha[4] = {th.x, th.y, th.z, th.w};

    float ns[4];
    #pragma unroll
    for (int i = 0; i < 4; ++i) {
        float acc = 3.0f * mw[i + 1];                  // center (self)
        acc += wa[0][i] * tw[i];
        acc += wa[1][i] * tw[i + 1];
        acc += wa[2][i] * tw[i + 2];
        acc += wa[3][i] * mw[i];
        acc += wa[4][i] * mw[i + 2];
        acc += wa[5][i] * bw[i];
        acc += wa[6][i] * bw[i + 1];
        acc += wa[7][i] * bw[i + 2];
        ns[i] = (acc > tha[i]) ? 1.0f : 0.0f;
    }
    float4 outv = make_float4(ns[0], ns[1], ns[2], ns[3]);
    *(float4*)(sout + idx) = outv;
    if (out_masks)
        *(float4*)(out_masks + idx) = outv;
}

__global__ void valid_kernel(const float* __restrict__ masks,
                             float* __restrict__ out_valid) {
    int b = blockIdx.x;
    int tid = threadIdx.x;     // 256
    const float* mb = masks + (size_t)b * HW;
    float cnt = 0.0f;
    for (int p = tid * 4; p < HW; p += 256 * 4) {
        float4 v = *(const float4*)(mb + p);
        cnt += v.x + v.y + v.z + v.w;
    }
    __shared__ float red[256];
    red[tid] = cnt;
    __syncthreads();
    for (int s = 128; s > 0; s >>= 1) {
        if (tid < s) red[tid] += red[tid + s];
        __syncthreads();
    }
    if (tid == 0) {
        float c = red[0];
        out_valid[b] = (c >= 16384.0f * 0.05f && c <= 16384.0f * 0.95f) ? 1.0f : 0.0f;
    }
}

// ================= launch =================

extern "C" void kernel_launch(void* const* d_in, const int* in_sizes, int n_in,
                              void* d_out, int out_size) {
    const float* seg_masks   = (const float*)d_in[0];   // 256*128*128
    const float* cate_scores = (const float*)d_in[1];   // 256
    const float* feature_map = (const float*)d_in[2];   // 64*3*128*128
    const float* x           = (const float*)d_in[3];   // 64*1*128*128
    const float* targets     = (const float*)d_in[4];   // 64*1*128*128
    const int*   cate_labels = (const int*)d_in[5];     // 256

    float* out_scores = (float*)d_out;                  // [256]
    float* out_masks  = out_scores + NMS_N;             // [64*128*128]
    float* out_valid  = out_masks + NPIX;               // [64]

    // ---- NMS ----
    pack_kernel<<<NMS_N, 512>>>(seg_masks);
    nms_iou_kernel<<<NMS_N, NMS_N>>>(cate_labels);
    nms_coef_kernel<<<NMS_N, NMS_N>>>(cate_scores, out_scores);

    // ---- CRF ----
    {
        int threads = 256;
        int blocks  = (NPIX + threads - 1) / threads;
        crf_weights_kernel<<<blocks, threads>>>(feature_map, x, targets);
    }

    // state base pointers (skip the 128-float front pad)
    float* s0 = nullptr; float* s1 = nullptr;
    cudaGetSymbolAddress((void**)&s0, g_state);
    s1 = s0 + (NPIX + 256);
    s0 += 128; s1 += 128;

    int threads = 256;
    int blocks  = (NPIX / 4 + threads - 1) / threads;
    float* cur = s0; float* nxt = s1;
    for (int it = 0; it < 10; ++it) {
        float* om = (it == 9) ? out_masks : nullptr;
        crf_iter_kernel<<<blocks, threads>>>(cur, nxt, om);
        float* tmp = cur; cur = nxt; nxt = tmp;
    }

    valid_kernel<<<NB, 256>>>(out_masks, out_valid);
}

// round 3
// speedup vs baseline: 3.6018x; 1.0942x over previous
#include <cuda_runtime.h>
#include <cuda_bf16.h>
#include <math.h>

// ---------------- problem sizes ----------------
#define NMS_N   256
#define HW      16384          // 128*128
#define WORDS   512            // 16384/32
#define NB      64             // batch for CRF
#define NPIX    (NB*HW)        // 1,048,576
#define WPAD    160            // front pad for weight planes (>=129, %4==0)
#define SPAD    160            // front/back pad for state (>=129, %4==0)

// ---------------- device scratch (static, no allocation) ----------------
__device__ unsigned int g_packedT[WORDS * NMS_N];      // [word][mask]
__device__ float        g_sums[NMS_N];
__device__ float        g_dmat[NMS_N * NMS_N];
__device__ float        g_comp[NMS_N];

// symmetric weight planes: only E(0,+1), S(+1,0), SE(+1,+1), SW(+1,-1) stored.
// Mirror reads (W,N,NW,NE) land on the neighbor's stored weight; boundary
// mirrors land on stored-zero (OOB at generation) or the zero pad.
__device__ __align__(16) float g_wE [WPAD + NPIX];
__device__ __align__(16) float g_wS [WPAD + NPIX];
__device__ __align__(16) float g_wSE[WPAD + NPIX];
__device__ __align__(16) float g_wSW[WPAD + NPIX];

__device__ unsigned char g_t4[NPIX / 4];               // 4 target bits per byte
__device__ __align__(16) float g_sig[2][SPAD + NPIX + SPAD];  // states as +-1, pads 0

// ================= NMS =================

__global__ void pack_kernel(const float* __restrict__ seg) {
    int m   = blockIdx.x;
    int tid = threadIdx.x;         // 512 threads
    int warp = tid >> 5, lane = tid & 31;
    int cnt = 0;
    for (int w = warp; w < WORDS; w += 16) {
        float v = seg[(size_t)m * HW + w * 32 + lane];
        unsigned bal = __ballot_sync(0xffffffffu, v != 0.0f);
        if (lane == 0) {
            g_packedT[w * NMS_N + m] = bal;
            cnt += __popc(bal);
        }
    }
    __shared__ int scnt[16];
    if (lane == 0) scnt[warp] = cnt;
    __syncthreads();
    if (tid == 0) {
        int t = 0;
        for (int i = 0; i < 16; ++i) t += scnt[i];
        g_sums[m] = (float)t;
    }
}

__global__ void nms_iou_kernel(const int* __restrict__ labels) {
    int j = blockIdx.x;
    int i = threadIdx.x;
    __shared__ unsigned int smj[WORDS];
    for (int w = i; w < WORDS; w += NMS_N) smj[w] = g_packedT[w * NMS_N + j];
    __syncthreads();

    float d = 0.0f;
    if (i < j && labels[i] == labels[j]) {
        int inter = 0;
        #pragma unroll 4
        for (int w = 0; w < WORDS; ++w)
            inter += __popc(g_packedT[w * NMS_N + i] & smj[w]);
        float fi  = (float)inter;
        float uni = g_sums[j] + g_sums[i] - fi;
        d = fi / uni;
    }
    g_dmat[j * NMS_N + i] = d;

    __shared__ float red[NMS_N];
    red[i] = d;
    __syncthreads();
    for (int s = NMS_N / 2; s > 0; s >>= 1) {
        if (i < s) red[i] = fmaxf(red[i], red[i + s]);
        __syncthreads();
    }
    if (i == 0) g_comp[j] = red[0];
}

__global__ void nms_coef_kernel(const float* __restrict__ cate_scores,
                                float* __restrict__ out_scores) {
    int j = blockIdx.x;
    int i = threadIdx.x;
    float d  = g_dmat[j * NMS_N + i];
    float ci = g_comp[i];
    float v  = expf(-2.0f * d * d) / expf(-2.0f * ci * ci);
    __shared__ float red[NMS_N];
    red[i] = v;
    __syncthreads();
    for (int s = NMS_N / 2; s > 0; s >>= 1) {
        if (i < s) red[i] = fminf(red[i], red[i + s]);
        __syncthreads();
    }
    if (i == 0) out_scores[j] = cate_scores[j] * red[0];
}

// ================= CRF =================

__global__ void crf_weights_kernel(const float* __restrict__ fm,
                                   const float* __restrict__ x,
                                   const float* __restrict__ tg) {
    int idx = blockIdx.x * blockDim.x + threadIdx.x;
    if (idx >= NPIX) return;
    int b   = idx >> 14;
    int pix = idx & (HW - 1);
    int h   = pix >> 7, w = pix & 127;

    const float* fb = fm + (size_t)b * 3 * HW;
    float c0 = fb[pix] + 10.0f;
    float c1 = fb[HW + pix] + 10.0f;
    float c2 = fb[2 * HW + pix] + 10.0f;

    const int   di[4]  = {0, 1, 1, 1};
    const int   dj[4]  = {1, 0, 1, -1};
    const float sp[4]  = {1.0f / 1800.0f, 1.0f / 1800.0f, 2.0f / 1800.0f, 2.0f / 1800.0f};
    float wv[4];
    #pragma unroll
    for (int k = 0; k < 4; ++k) {
        int hh = h + di[k], ww = w + dj[k];
        float v = 0.0f;
        if (hh < 128 && ww >= 0 && ww < 128) {
            int np = hh * 128 + ww;
            float d0 = (fb[np] + 10.0f) - c0;
            float d1 = (fb[HW + np] + 10.0f) - c1;
            float d2 = (fb[2 * HW + np] + 10.0f) - c2;
            float ss = d0 * d0 + d1 * d1 + d2 * d2;
            v = 3.0f * expf(-ss * 2.0f - sp[k]);
        }
        wv[k] = v;
    }
    g_wE [WPAD + idx] = wv[0];
    g_wS [WPAD + idx] = wv[1];
    g_wSE[WPAD + idx] = wv[2];
    g_wSW[WPAD + idx] = wv[3];

    float xv = x[idx], tv = tg[idx];
    int tb = (tv > 0.5f) ? 1 : 0;
    unsigned bal = __ballot_sync(0xffffffffu, tb);
    int lane = threadIdx.x & 31;
    if ((lane & 3) == 0)
        g_t4[idx >> 2] = (unsigned char)((bal >> lane) & 0xF);

    g_sig[0][SPAD + idx] = (xv * tv > 0.5f) ? 1.0f : -1.0f;
}

// One CRF iteration: margin form, 4 pixels per thread, branch-free.
// new_on = t && ( 3*sig_c + sum_8dirs w * sig_neighbor > 0 )
__global__ void crf_iter_kernel(const float* __restrict__ sin,
                                float* __restrict__ sout,
                                float* __restrict__ out_masks) {
    int t4 = blockIdx.x * blockDim.x + threadIdx.x;
    if (t4 >= NPIX / 4) return;
    int idx = t4 << 2;

    // states: sig in {+1,-1}, zero pads absorb OOB (matching zero weights)
    const float* sb = sin + SPAD + idx;
    float4 cu = *(const float4*)(sb - 128);
    float4 cm = *(const float4*)(sb);
    float4 cd = *(const float4*)(sb + 128);
    float lu = sb[-129], ru = sb[-124];
    float lm = sb[-1],   rm = sb[4];
    float ld = sb[127],  rd = sb[132];

    float tw[6] = {lu, cu.x, cu.y, cu.z, cu.w, ru};
    float mw[6] = {lm, cm.x, cm.y, cm.z, cm.w, rm};
    float bw[6] = {ld, cd.x, cd.y, cd.z, cd.w, rd};

    const float* pE  = g_wE  + WPAD + idx;
    const float* pS  = g_wS  + WPAD + idx;
    const float* pSE = g_wSE + WPAD + idx;
    const float* pSW = g_wSW + WPAD + idx;

    float4 eO  = *(const float4*)(pE);
    float  eW  = pE[-1];
    float4 sO  = *(const float4*)(pS);
    float4 sM  = *(const float4*)(pS - 128);
    float4 seO = *(const float4*)(pSE);
    float4 seM = *(const float4*)(pSE - 128);
    float  seS = pSE[-129];
    float4 swO = *(const float4*)(pSW);
    float4 swM = *(const float4*)(pSW - 128);
    float  swS = pSW[-124];

    float eOa[4]  = {eO.x, eO.y, eO.z, eO.w};
    float sOa[4]  = {sO.x, sO.y, sO.z, sO.w};
    float sMa[4]  = {sM.x, sM.y, sM.z, sM.w};
    float seOa[4] = {seO.x, seO.y, seO.z, seO.w};
    float seMa[4] = {seM.x, seM.y, seM.z, seM.w};
    float swOa[4] = {swO.x, swO.y, swO.z, swO.w};
    float swMa[4] = {swM.x, swM.y, swM.z, swM.w};

    unsigned int tb = g_t4[t4];

    float ns[4], msk[4];
    #pragma unroll
    for (int i = 0; i < 4; ++i) {
        float wW  = (i == 0) ? eW  : eOa[i - 1];
        float wNW = (i == 0) ? seS : seMa[i - 1];
        float wNE = (i == 3) ? swS : swMa[i + 1];
        float m = 3.0f * mw[i + 1];
        m += eOa[i]  * mw[i + 2];   // E
        m += wW      * mw[i];       // W
        m += sOa[i]  * bw[i + 1];   // S
        m += sMa[i]  * tw[i + 1];   // N
        m += seOa[i] * bw[i + 2];   // SE
        m += wNW     * tw[i];       // NW
        m += swOa[i] * bw[i];       // SW
        m += wNE     * tw[i + 2];   // NE
        bool on = (m > 0.0f) && ((tb >> i) & 1u);
        ns[i]  = on ? 1.0f : -1.0f;
        msk[i] = on ? 1.0f : 0.0f;
    }
    *(float4*)(sout + SPAD + idx) = make_float4(ns[0], ns[1], ns[2], ns[3]);
    if (out_masks)
        *(float4*)(out_masks + idx) = make_float4(msk[0], msk[1], msk[2], msk[3]);
}

__global__ void valid_kernel(const float* __restrict__ masks,
                             float* __restrict__ out_valid) {
    int b = blockIdx.x;
    int tid = threadIdx.x;     // 256
    const float* mb = masks + (size_t)b * HW;
    float cnt = 0.0f;
    for (int p = tid * 4; p < HW; p += 256 * 4) {
        float4 v = *(const float4*)(mb + p);
        cnt += v.x + v.y + v.z + v.w;
    }
    __shared__ float red[256];
    red[tid] = cnt;
    __syncthreads();
    for (int s = 128; s > 0; s >>= 1) {
        if (tid < s) red[tid] += red[tid + s];
        __syncthreads();
    }
    if (tid == 0) {
        float c = red[0];
        out_valid[b] = (c >= 16384.0f * 0.05f && c <= 16384.0f * 0.95f) ? 1.0f : 0.0f;
    }
}

// ================= launch =================

extern "C" void kernel_launch(void* const* d_in, const int* in_sizes, int n_in,
                              void* d_out, int out_size) {
    const float* seg_masks   = (const float*)d_in[0];
    const float* cate_scores = (const float*)d_in[1];
    const float* feature_map = (const float*)d_in[2];
    const float* x           = (const float*)d_in[3];
    const float* targets     = (const float*)d_in[4];
    const int*   cate_labels = (const int*)d_in[5];

    float* out_scores = (float*)d_out;                  // [256]
    float* out_masks  = out_scores + NMS_N;             // [64*128*128]
    float* out_valid  = out_masks + NPIX;               // [64]

    // ---- NMS ----
    pack_kernel<<<NMS_N, 512>>>(seg_masks);
    nms_iou_kernel<<<NMS_N, NMS_N>>>(cate_labels);
    nms_coef_kernel<<<NMS_N, NMS_N>>>(cate_scores, out_scores);

    // ---- CRF ----
    {
        int threads = 256;
        int blocks  = (NPIX + threads - 1) / threads;
        crf_weights_kernel<<<blocks, threads>>>(feature_map, x, targets);
    }

    float* sbase = nullptr;
    cudaGetSymbolAddress((void**)&sbase, g_sig);
    float* s0 = sbase;                          // plane 0 (index includes SPAD inside kernel)
    float* s1 = sbase + (SPAD + NPIX + SPAD);   // plane 1

    int threads = 256;
    int blocks  = (NPIX / 4 + threads - 1) / threads;
    float* cur = s0; float* nxt = s1;
    for (int it = 0; it < 10; ++it) {
        float* om = (it == 9) ? out_masks : nullptr;
        crf_iter_kernel<<<blocks, threads>>>(cur, nxt, om);
        float* tmp = cur; cur = nxt; nxt = tmp;
    }

    valid_kernel<<<NB, 256>>>(out_masks, out_valid);
}